// round 4
// baseline (speedup 1.0000x reference)
#include <cuda_runtime.h>
#include <cuda_bf16.h>
#include <cstdint>

#define BB   64
#define TT   512
#define DD   128
#define HH   256
#define G4H  1024

typedef unsigned long long u64;

// ---------------------------------------------------------------------------
// Device scratch
// ---------------------------------------------------------------------------
__device__ float g_Gv[(size_t)BB * TT * G4H];
__device__ float g_Gl[(size_t)BB * TT * G4H];
__device__ float g_Gu[(size_t)BB * TT * G4H];
__device__ float4 g_Hf4[2 * HH * BB];     // [pp][h*BB + b] = (v, m, r, _)
__device__ unsigned int g_bar[8];         // per-batch-group barrier counters

// ---------------------------------------------------------------------------
// Helpers
// ---------------------------------------------------------------------------
__device__ __forceinline__ u64 fma2(u64 a, u64 b, u64 c) {
    u64 d; asm("fma.rn.f32x2 %0, %1, %2, %3;" : "=l"(d) : "l"(a), "l"(b), "l"(c)); return d;
}
__device__ __forceinline__ u64 add2(u64 a, u64 b) {
    u64 d; asm("add.rn.f32x2 %0, %1, %2;" : "=l"(d) : "l"(a), "l"(b)); return d;
}
__device__ __forceinline__ void upk(u64 v, float& lo, float& hi) {
    asm("mov.b64 {%0,%1}, %2;" : "=f"(lo), "=f"(hi) : "l"(v));
}
__device__ __forceinline__ float sigf(float x) {
    return __fdividef(1.0f, 1.0f + __expf(-x));
}
__device__ __forceinline__ float tanhf_(float x) {
    return __fdividef(2.0f, 1.0f + __expf(-2.0f * x)) - 1.0f;
}
__device__ __forceinline__ float min4f(float a, float b, float c, float d) {
    return fminf(fminf(a, b), fminf(c, d));
}
__device__ __forceinline__ float max4f(float a, float b, float c, float d) {
    return fmaxf(fmaxf(a, b), fmaxf(c, d));
}

// ---------------------------------------------------------------------------
// Kernel 1: gx interval GEMM (FFMA2, direct u64 smem loads). Resets barriers.
// ---------------------------------------------------------------------------
#define GM 64
#define GN 64
#define GK 16

__global__ __launch_bounds__(256) void gx_gemm_kernel(
    const float* __restrict__ xv, const float* __restrict__ xl,
    const float* __restrict__ xu, const float* __restrict__ W,
    const float* __restrict__ bias)
{
    if (blockIdx.x == 0 && blockIdx.y == 0 && threadIdx.x < 8)
        g_bar[threadIdx.x] = 0u;

    __shared__ float sAvD[GK][2 * GM + 4];
    __shared__ float sAmD[GK][2 * GM + 4];
    __shared__ float sArD[GK][2 * GM + 4];
    __shared__ float sB [GK][GN + 4];
    __shared__ float sBa[GK][GN + 4];

    const int n0 = blockIdx.x * GN;
    const int m0 = blockIdx.y * GM;
    const int tid = threadIdx.x;
    const int tx = tid & 15;
    const int ty = tid >> 4;

    u64 accv[4][2], accm[4][2], accr[4][2];
#pragma unroll
    for (int i = 0; i < 4; i++)
#pragma unroll
        for (int j = 0; j < 2; j++) { accv[i][j] = 0ull; accm[i][j] = 0ull; accr[i][j] = 0ull; }

    const int ml = tid >> 2;
    const int kq = tid & 3;

    for (int k0 = 0; k0 < DD; k0 += GK) {
        {
            const float4 v4 = *(const float4*)(xv + (size_t)(m0 + ml) * DD + k0 + kq * 4);
            const float4 l4 = *(const float4*)(xl + (size_t)(m0 + ml) * DD + k0 + kq * 4);
            const float4 u4 = *(const float4*)(xu + (size_t)(m0 + ml) * DD + k0 + kq * 4);
            const float vv[4] = {v4.x, v4.y, v4.z, v4.w};
            const float ll[4] = {l4.x, l4.y, l4.z, l4.w};
            const float uu[4] = {u4.x, u4.y, u4.z, u4.w};
#pragma unroll
            for (int j = 0; j < 4; j++) {
                const int k = kq * 4 + j;
                const float mu = 0.5f * (ll[j] + uu[j]);
                const float rr = 0.5f * (uu[j] - ll[j]);
                ((float2*)&sAvD[k][0])[ml] = make_float2(vv[j], vv[j]);
                ((float2*)&sAmD[k][0])[ml] = make_float2(mu, mu);
                ((float2*)&sArD[k][0])[ml] = make_float2(rr, rr);
            }
        }
        {
            const float4 w4 = *(const float4*)(W + (size_t)(n0 + ml) * DD + k0 + kq * 4);
            const float ww[4] = {w4.x, w4.y, w4.z, w4.w};
#pragma unroll
            for (int j = 0; j < 4; j++) {
                sB [kq * 4 + j][ml] = ww[j];
                sBa[kq * 4 + j][ml] = fabsf(ww[j]);
            }
        }
        __syncthreads();

#pragma unroll
        for (int k = 0; k < GK; k++) {
            const u64 b01 = *(const u64*)&sB [k][tx * 4];
            const u64 b23 = *(const u64*)&sB [k][tx * 4 + 2];
            const u64 a01 = *(const u64*)&sBa[k][tx * 4];
            const u64 a23 = *(const u64*)&sBa[k][tx * 4 + 2];
#pragma unroll
            for (int i = 0; i < 4; i++) {
                const u64 av = *(const u64*)&sAvD[k][2 * (4 * ty + i)];
                const u64 am = *(const u64*)&sAmD[k][2 * (4 * ty + i)];
                const u64 ar = *(const u64*)&sArD[k][2 * (4 * ty + i)];
                accv[i][0] = fma2(av, b01, accv[i][0]);
                accv[i][1] = fma2(av, b23, accv[i][1]);
                accm[i][0] = fma2(am, b01, accm[i][0]);
                accm[i][1] = fma2(am, b23, accm[i][1]);
                accr[i][0] = fma2(ar, a01, accr[i][0]);
                accr[i][1] = fma2(ar, a23, accr[i][1]);
            }
        }
        __syncthreads();
    }

    float bb4[4];
#pragma unroll
    for (int j = 0; j < 4; j++) bb4[j] = bias[n0 + tx * 4 + j];
#pragma unroll
    for (int i = 0; i < 4; i++) {
        const int m = m0 + ty * 4 + i;
        const size_t o = (size_t)m * G4H + n0 + tx * 4;
        float v0, v1, v2, v3, q0, q1, q2, q3, r0, r1, r2, r3;
        upk(accv[i][0], v0, v1); upk(accv[i][1], v2, v3);
        upk(accm[i][0], q0, q1); upk(accm[i][1], q2, q3);
        upk(accr[i][0], r0, r1); upk(accr[i][1], r2, r3);
        *(float4*)(g_Gv + o) = make_float4(v0 + bb4[0], v1 + bb4[1], v2 + bb4[2], v3 + bb4[3]);
        *(float4*)(g_Gl + o) = make_float4(q0 + bb4[0] - r0, q1 + bb4[1] - r1, q2 + bb4[2] - r2, q3 + bb4[3] - r3);
        *(float4*)(g_Gu + o) = make_float4(q0 + bb4[0] + r0, q1 + bb4[1] + r1, q2 + bb4[2] + r2, q3 + bb4[3] + r3);
    }
}

// ---------------------------------------------------------------------------
// Kernel 2: persistent scan. 128 CTAs x 512 thr (1/SM, 4 warps/SMSP).
// CTA owns 8 batches x 16 h = 128 cells; each cell split across 4 k-quarter
// threads.  f32x2 inner loop: 2 LDS.128 + 3 LDS.64 + 6 FFMA2 per k.
// 8 independent batch-groups (16 CTAs each) with per-group barriers.
// ---------------------------------------------------------------------------
#define NCTA 128
#define NTHR 512

// smem (float offsets):
//  sW   [0,     16384) : [256 k][16 h][4 g]
//  sWa  [16384, 32768) : |W|
//  sHv  [32768, 36864) : float2[256 k][8 b]  (h val duplicated)
//  sHm  [36864, 40960) : float2               (h mid duplicated)
//  sHr  [40960, 45056) : float2               (h rad duplicated)
//  sRed [45056, 49664) : u64[6][3][128]
#define SM_HV 32768
#define SM_HM 36864
#define SM_HR 40960
#define SM_RED 45056
#define SMEM_FLOATS 49664

__global__ __launch_bounds__(NTHR, 1) void scan_kernel(
    const float* __restrict__ Whh, const float* __restrict__ h0,
    const float* __restrict__ c0, float* __restrict__ out)
{
    extern __shared__ float smem[];
    float* sW  = smem;
    float* sWa = smem + 16384;
    float2* sHv2 = (float2*)(smem + SM_HV);
    float2* sHm2 = (float2*)(smem + SM_HM);
    float2* sHr2 = (float2*)(smem + SM_HR);
    u64*    sRed = (u64*)(smem + SM_RED);

    const int tid = threadIdx.x;
    const int gb = blockIdx.x >> 4;      // batch group 0..7
    const int hc = blockIdx.x & 15;      // h chunk 0..15
    const int c  = tid & 127;            // cell id in CTA
    const int kq = tid >> 7;             // k quarter 0..3
    const int bL = c & 7;
    const int hL = c >> 3;               // 0..15
    const int b  = gb * 8 + bL;
    const int hg = hc * 16 + hL;

    // stage W (+|W|) once: sW[k*64 + hh*4 + g]
    for (int idx = tid; idx < 16384; idx += NTHR) {
        const int g  = idx & 3;
        const int hh = (idx >> 2) & 15;
        const int k  = idx >> 6;
        const float w = Whh[(size_t)(g * HH + hc * 16 + hh) * HH + k];
        sW[idx]  = w;
        sWa[idx] = fabsf(w);
    }

    float cv = 0.f, cl = 0.f, cu = 0.f;
    if (kq == 0) { cv = c0[b * HH + hg]; cl = cv; cu = cv; }

    const int kbase = kq * 64;
    unsigned int* barp = &g_bar[gb];
    const ulonglong2* wp = (const ulonglong2*)sW;
    const ulonglong2* qp = (const ulonglong2*)sWa;
    const u64* hvp = (const u64*)sHv2;
    const u64* hmp = (const u64*)sHm2;
    const u64* hrp = (const u64*)sHr2;

    for (int t = 0; t < TT; t++) {
        // gx prefetch for this step (kq==0 only; issued before barrier)
        float gv0, gl0, gu0, gv1, gl1, gu1, gv2, gl2, gu2, gv3, gl3, gu3;
        if (kq == 0) {
            const int gidx = ((b << 9) + t) << 10;
            gv0 = __ldcs(g_Gv + gidx + hg);       gl0 = __ldcs(g_Gl + gidx + hg);       gu0 = __ldcs(g_Gu + gidx + hg);
            gv1 = __ldcs(g_Gv + gidx + 256 + hg); gl1 = __ldcs(g_Gl + gidx + 256 + hg); gu1 = __ldcs(g_Gu + gidx + 256 + hg);
            gv2 = __ldcs(g_Gv + gidx + 512 + hg); gl2 = __ldcs(g_Gl + gidx + 512 + hg); gu2 = __ldcs(g_Gu + gidx + 512 + hg);
            gv3 = __ldcs(g_Gv + gidx + 768 + hg); gl3 = __ldcs(g_Gl + gidx + 768 + hg); gu3 = __ldcs(g_Gu + gidx + 768 + hg);
        }

        if (t > 0) {
            __syncthreads();
            if (tid == 0) {
                asm volatile("red.release.gpu.global.add.u32 [%0], 1;" :: "l"(barp) : "memory");
                unsigned int v;
                do {
                    asm volatile("ld.acquire.gpu.global.u32 %0, [%1];" : "=r"(v) : "l"(barp) : "memory");
                } while (v < (unsigned)t * 16u);
            }
            __syncthreads();
        }

        // stage previous h in duplicated-pair form: sH*[k*8 + b] = (x, x)
        if (t == 0) {
            for (int idx = tid; idx < 2048; idx += NTHR) {
                const int k = idx >> 3, bb = idx & 7;
                const float v = h0[(gb * 8 + bb) * HH + k];
                sHv2[idx] = make_float2(v, v);
                sHm2[idx] = make_float2(v, v);
                sHr2[idx] = make_float2(0.f, 0.f);
            }
        } else {
            const float4* src = g_Hf4 + ((t - 1) & 1) * (HH * BB) + gb * 8;
            for (int idx = tid; idx < 2048; idx += NTHR) {
                const int k = idx >> 3, bb = idx & 7;
                const float4 f = __ldcg(src + k * BB + bb);
                sHv2[idx] = make_float2(f.x, f.x);
                sHm2[idx] = make_float2(f.y, f.y);
                sHr2[idx] = make_float2(f.z, f.z);
            }
        }
        __syncthreads();

        // quarter k-loop: 64 iters, 2 LDS.128 + 3 LDS.64 + 6 FFMA2
        u64 av01 = 0ull, av23 = 0ull, am01 = 0ull, am23 = 0ull, ar01 = 0ull, ar23 = 0ull;
#pragma unroll 8
        for (int k = kbase; k < kbase + 64; k++) {
            const ulonglong2 w = wp[k * 16 + hL];
            const ulonglong2 q = qp[k * 16 + hL];
            const u64 hv = hvp[k * 8 + bL];
            const u64 hm = hmp[k * 8 + bL];
            const u64 hr = hrp[k * 8 + bL];
            av01 = fma2(hv, w.x, av01);
            av23 = fma2(hv, w.y, av23);
            am01 = fma2(hm, w.x, am01);
            am23 = fma2(hm, w.y, am23);
            ar01 = fma2(hr, q.x, ar01);
            ar23 = fma2(hr, q.y, ar23);
        }

        // combine k-quarters: layout sRed[j][s][c], j=0..5, s=kq-1
        if (kq > 0) {
            const int s = kq - 1;
            sRed[(0 * 3 + s) * 128 + c] = av01;
            sRed[(1 * 3 + s) * 128 + c] = av23;
            sRed[(2 * 3 + s) * 128 + c] = am01;
            sRed[(3 * 3 + s) * 128 + c] = am23;
            sRed[(4 * 3 + s) * 128 + c] = ar01;
            sRed[(5 * 3 + s) * 128 + c] = ar23;
        }
        __syncthreads();

        if (kq == 0) {
#pragma unroll
            for (int s = 0; s < 3; s++) {
                av01 = add2(av01, sRed[(0 * 3 + s) * 128 + c]);
                av23 = add2(av23, sRed[(1 * 3 + s) * 128 + c]);
                am01 = add2(am01, sRed[(2 * 3 + s) * 128 + c]);
                am23 = add2(am23, sRed[(3 * 3 + s) * 128 + c]);
                ar01 = add2(ar01, sRed[(4 * 3 + s) * 128 + c]);
                ar23 = add2(ar23, sRed[(5 * 3 + s) * 128 + c]);
            }

            float av0, av1, av2, av3, am0, am1, am2, am3, ar0, ar1, ar2, ar3;
            upk(av01, av0, av1); upk(av23, av2, av3);
            upk(am01, am0, am1); upk(am23, am2, am3);
            upk(ar01, ar0, ar1); upk(ar23, ar2, ar3);

            const float pv0 = gv0 + av0, pl0 = gl0 + am0 - ar0, pu0 = gu0 + am0 + ar0;
            const float pv1 = gv1 + av1, pl1 = gl1 + am1 - ar1, pu1 = gu1 + am1 + ar1;
            const float pv2 = gv2 + av2, pl2 = gl2 + am2 - ar2, pu2 = gu2 + am2 + ar2;
            const float pv3 = gv3 + av3, pl3 = gl3 + am3 - ar3, pu3 = gu3 + am3 + ar3;

            const float iv = sigf(pv0), il = sigf(pl0), iu = sigf(pu0);
            const float fv = sigf(pv1), fl = sigf(pl1), fu = sigf(pu1);
            const float gv = tanhf_(pv2), gl = tanhf_(pl2), gu = tanhf_(pu2);
            const float ov = sigf(pv3), ol = sigf(pl3), ou = sigf(pu3);

            const float t1 = fl * cl, t2 = fl * cu, t3 = fu * cl, t4 = fu * cu;
            const float s1 = il * gl, s2 = il * gu, s3 = iu * gl, s4 = iu * gu;
            cv = fv * cv + iv * gv;
            cl = min4f(t1, t2, t3, t4) + min4f(s1, s2, s3, s4);
            cu = max4f(t1, t2, t3, t4) + max4f(s1, s2, s3, s4);

            const float tv = tanhf_(cv), tl = tanhf_(cl), tu = tanhf_(cu);
            const float u1 = ol * tl, u2 = ol * tu, u3 = ou * tl, u4 = ou * tu;
            const float hn_l = min4f(u1, u2, u3, u4);
            const float hn_u = max4f(u1, u2, u3, u4);
            const float hn_v = ov * tv;

            const float hm = 0.5f * (hn_l + hn_u);
            const float hr = 0.5f * (hn_u - hn_l);
            __stcg(g_Hf4 + (t & 1) * (HH * BB) + hg * BB + b,
                   make_float4(hn_v, hm, hr, 0.f));

            const size_t obase = ((size_t)(b << 9) + t) * HH + hg;
            out[obase] = hn_v;
            out[(size_t)BB * TT * HH + obase] = hn_l;
            out[2 * (size_t)BB * TT * HH + obase] = hn_u;
        }
    }
}

// ---------------------------------------------------------------------------
// Launch
// ---------------------------------------------------------------------------
extern "C" void kernel_launch(void* const* d_in, const int* in_sizes, int n_in,
                              void* d_out, int out_size)
{
    const float* xv   = (const float*)d_in[0];
    const float* xl   = (const float*)d_in[1];
    const float* xu   = (const float*)d_in[2];
    const float* Wih  = (const float*)d_in[3];
    const float* Whh  = (const float*)d_in[4];
    const float* bias = (const float*)d_in[5];
    const float* h0   = (const float*)d_in[6];
    const float* c0   = (const float*)d_in[7];
    float* out = (float*)d_out;

    const int smem_bytes = SMEM_FLOATS * sizeof(float);   // ~194 KB
    cudaFuncSetAttribute(scan_kernel, cudaFuncAttributeMaxDynamicSharedMemorySize, smem_bytes);

    gx_gemm_kernel<<<dim3(G4H / GN, (BB * TT) / GM), 256>>>(xv, xl, xu, Wih, bias);
    scan_kernel<<<NCTA, NTHR, smem_bytes>>>(Whh, h0, c0, out);
}

// round 5
// speedup vs baseline: 1.2167x; 1.2167x over previous
#include <cuda_runtime.h>
#include <cuda_bf16.h>
#include <cstdint>

#define BB   64
#define TT   512
#define DD   128
#define HH   256
#define G4H  1024

typedef unsigned long long u64;

// ---------------------------------------------------------------------------
// Device scratch
// ---------------------------------------------------------------------------
__device__ float g_Gv[(size_t)BB * TT * G4H];
__device__ float g_Gl[(size_t)BB * TT * G4H];
__device__ float g_Gu[(size_t)BB * TT * G4H];
__device__ float4 g_Hf4[2 * HH * BB];     // [pp][h*BB + b] = (v, m, r, _)
__device__ unsigned int g_bar[8];         // per-batch-group barrier counters

// ---------------------------------------------------------------------------
// Helpers
// ---------------------------------------------------------------------------
__device__ __forceinline__ u64 pk(float lo, float hi) {
    u64 r; asm("mov.b64 %0, {%1,%2};" : "=l"(r) : "f"(lo), "f"(hi)); return r;
}
__device__ __forceinline__ u64 fma2(u64 a, u64 b, u64 c) {
    u64 d; asm("fma.rn.f32x2 %0, %1, %2, %3;" : "=l"(d) : "l"(a), "l"(b), "l"(c)); return d;
}
__device__ __forceinline__ u64 add2(u64 a, u64 b) {
    u64 d; asm("add.rn.f32x2 %0, %1, %2;" : "=l"(d) : "l"(a), "l"(b)); return d;
}
__device__ __forceinline__ void upk(u64 v, float& lo, float& hi) {
    asm("mov.b64 {%0,%1}, %2;" : "=f"(lo), "=f"(hi) : "l"(v));
}
__device__ __forceinline__ float sigf(float x) {
    return __fdividef(1.0f, 1.0f + __expf(-x));
}
__device__ __forceinline__ float tanhf_(float x) {
    return __fdividef(2.0f, 1.0f + __expf(-2.0f * x)) - 1.0f;
}
__device__ __forceinline__ float min4f(float a, float b, float c, float d) {
    return fminf(fminf(a, b), fminf(c, d));
}
__device__ __forceinline__ float max4f(float a, float b, float c, float d) {
    return fmaxf(fmaxf(a, b), fmaxf(c, d));
}

// ---------------------------------------------------------------------------
// Kernel 1: gx interval GEMM (unchanged, FFMA2). Resets barriers.
// ---------------------------------------------------------------------------
#define GM 64
#define GN 64
#define GK 16

__global__ __launch_bounds__(256) void gx_gemm_kernel(
    const float* __restrict__ xv, const float* __restrict__ xl,
    const float* __restrict__ xu, const float* __restrict__ W,
    const float* __restrict__ bias)
{
    if (blockIdx.x == 0 && blockIdx.y == 0 && threadIdx.x < 8)
        g_bar[threadIdx.x] = 0u;

    __shared__ float sAvD[GK][2 * GM + 4];
    __shared__ float sAmD[GK][2 * GM + 4];
    __shared__ float sArD[GK][2 * GM + 4];
    __shared__ float sB [GK][GN + 4];
    __shared__ float sBa[GK][GN + 4];

    const int n0 = blockIdx.x * GN;
    const int m0 = blockIdx.y * GM;
    const int tid = threadIdx.x;
    const int tx = tid & 15;
    const int ty = tid >> 4;

    u64 accv[4][2], accm[4][2], accr[4][2];
#pragma unroll
    for (int i = 0; i < 4; i++)
#pragma unroll
        for (int j = 0; j < 2; j++) { accv[i][j] = 0ull; accm[i][j] = 0ull; accr[i][j] = 0ull; }

    const int ml = tid >> 2;
    const int kq = tid & 3;

    for (int k0 = 0; k0 < DD; k0 += GK) {
        {
            const float4 v4 = *(const float4*)(xv + (size_t)(m0 + ml) * DD + k0 + kq * 4);
            const float4 l4 = *(const float4*)(xl + (size_t)(m0 + ml) * DD + k0 + kq * 4);
            const float4 u4 = *(const float4*)(xu + (size_t)(m0 + ml) * DD + k0 + kq * 4);
            const float vv[4] = {v4.x, v4.y, v4.z, v4.w};
            const float ll[4] = {l4.x, l4.y, l4.z, l4.w};
            const float uu[4] = {u4.x, u4.y, u4.z, u4.w};
#pragma unroll
            for (int j = 0; j < 4; j++) {
                const int k = kq * 4 + j;
                const float mu = 0.5f * (ll[j] + uu[j]);
                const float rr = 0.5f * (uu[j] - ll[j]);
                ((float2*)&sAvD[k][0])[ml] = make_float2(vv[j], vv[j]);
                ((float2*)&sAmD[k][0])[ml] = make_float2(mu, mu);
                ((float2*)&sArD[k][0])[ml] = make_float2(rr, rr);
            }
        }
        {
            const float4 w4 = *(const float4*)(W + (size_t)(n0 + ml) * DD + k0 + kq * 4);
            const float ww[4] = {w4.x, w4.y, w4.z, w4.w};
#pragma unroll
            for (int j = 0; j < 4; j++) {
                sB [kq * 4 + j][ml] = ww[j];
                sBa[kq * 4 + j][ml] = fabsf(ww[j]);
            }
        }
        __syncthreads();

#pragma unroll
        for (int k = 0; k < GK; k++) {
            const u64 b01 = *(const u64*)&sB [k][tx * 4];
            const u64 b23 = *(const u64*)&sB [k][tx * 4 + 2];
            const u64 a01 = *(const u64*)&sBa[k][tx * 4];
            const u64 a23 = *(const u64*)&sBa[k][tx * 4 + 2];
#pragma unroll
            for (int i = 0; i < 4; i++) {
                const u64 av = *(const u64*)&sAvD[k][2 * (4 * ty + i)];
                const u64 am = *(const u64*)&sAmD[k][2 * (4 * ty + i)];
                const u64 ar = *(const u64*)&sArD[k][2 * (4 * ty + i)];
                accv[i][0] = fma2(av, b01, accv[i][0]);
                accv[i][1] = fma2(av, b23, accv[i][1]);
                accm[i][0] = fma2(am, b01, accm[i][0]);
                accm[i][1] = fma2(am, b23, accm[i][1]);
                accr[i][0] = fma2(ar, a01, accr[i][0]);
                accr[i][1] = fma2(ar, a23, accr[i][1]);
            }
        }
        __syncthreads();
    }

    float bb4[4];
#pragma unroll
    for (int j = 0; j < 4; j++) bb4[j] = bias[n0 + tx * 4 + j];
#pragma unroll
    for (int i = 0; i < 4; i++) {
        const int m = m0 + ty * 4 + i;
        const size_t o = (size_t)m * G4H + n0 + tx * 4;
        float v0, v1, v2, v3, q0, q1, q2, q3, r0, r1, r2, r3;
        upk(accv[i][0], v0, v1); upk(accv[i][1], v2, v3);
        upk(accm[i][0], q0, q1); upk(accm[i][1], q2, q3);
        upk(accr[i][0], r0, r1); upk(accr[i][1], r2, r3);
        *(float4*)(g_Gv + o) = make_float4(v0 + bb4[0], v1 + bb4[1], v2 + bb4[2], v3 + bb4[3]);
        *(float4*)(g_Gl + o) = make_float4(q0 + bb4[0] - r0, q1 + bb4[1] - r1, q2 + bb4[2] - r2, q3 + bb4[3] - r3);
        *(float4*)(g_Gu + o) = make_float4(q0 + bb4[0] + r0, q1 + bb4[1] + r1, q2 + bb4[2] + r2, q3 + bb4[3] + r3);
    }
}

// ---------------------------------------------------------------------------
// Kernel 2: persistent scan, W-in-registers edition.
// 128 CTAs x 512 thr (1/SM). CTA = (batch group gb: 8 batches) x (h chunk hc:
// 16 h). Outputs per CTA/step: 64 gate-rows (16h x 4g) x 8 batches x 3
// intervals.  Thread (kgroup 0..7, m 0..63): holds W[m][kslice=32] in regs
// forever; k-loop reads only h via same-address broadcast LDS (1 wf each).
// ---------------------------------------------------------------------------
#define NCTA 128
#define NTHR 512
#define KSL  32

// smem float offsets:
//  sH   [0,     6144)  : float [256 k][24] = (hv[8], hm[8], hr[8])
//  sRed [6144,  20480) : u64 [512][14] (12 used, pitch 14)
//  sT   [20480, 22016) : u64 [12][16][4]
#define SM_RED 6144
#define SM_T   20480
#define SMEM_FLOATS 22016

__global__ __launch_bounds__(NTHR, 1) void scan_kernel(
    const float* __restrict__ Whh, const float* __restrict__ h0,
    const float* __restrict__ c0, float* __restrict__ out)
{
    extern __shared__ float smem[];
    float* sH   = smem;
    u64*   sRed = (u64*)(smem + SM_RED);
    u64*   sT   = (u64*)(smem + SM_T);
    float* sTf  = (float*)sT;

    const int tid = threadIdx.x;
    const int gb = blockIdx.x >> 4;      // batch group 0..7
    const int hc = blockIdx.x & 15;      // h chunk 0..15
    const int kgroup = tid >> 6;         // 0..7
    const int m = tid & 63;              // gate-row 0..63
    const int hL = m >> 2;               // 0..15
    const int g  = m & 3;                // 0..3
    const int kbase = kgroup * KSL;

    // --- W slice into registers (forever) ---
    float wreg[KSL];
    {
        const float* wrow = Whh + (size_t)(g * HH + hc * 16 + hL) * HH + kbase;
#pragma unroll
        for (int i = 0; i < KSL / 4; i++) {
            const float4 w4 = *(const float4*)(wrow + 4 * i);
            wreg[4 * i + 0] = w4.x; wreg[4 * i + 1] = w4.y;
            wreg[4 * i + 2] = w4.z; wreg[4 * i + 3] = w4.w;
        }
    }

    // --- pointwise cell state (tid < 128): cell (ph, pb) ---
    const int pb = tid & 7;
    const int ph = (tid >> 3) & 15;
    const int bglob = gb * 8 + pb;
    const int hg = hc * 16 + ph;
    float cv = 0.f, cl = 0.f, cu = 0.f;
    if (tid < 128) { cv = c0[bglob * HH + hg]; cl = cv; cu = cv; }

    unsigned int* barp = &g_bar[gb];

    for (int t = 0; t < TT; t++) {
        // gx prefetch (tid<128, before barrier)
        float gv0, gl0, gu0, gv1, gl1, gu1, gv2, gl2, gu2, gv3, gl3, gu3;
        if (tid < 128) {
            const int gidx = ((bglob << 9) + t) << 10;
            gv0 = __ldcs(g_Gv + gidx + hg);       gl0 = __ldcs(g_Gl + gidx + hg);       gu0 = __ldcs(g_Gu + gidx + hg);
            gv1 = __ldcs(g_Gv + gidx + 256 + hg); gl1 = __ldcs(g_Gl + gidx + 256 + hg); gu1 = __ldcs(g_Gu + gidx + 256 + hg);
            gv2 = __ldcs(g_Gv + gidx + 512 + hg); gl2 = __ldcs(g_Gl + gidx + 512 + hg); gu2 = __ldcs(g_Gu + gidx + 512 + hg);
            gv3 = __ldcs(g_Gv + gidx + 768 + hg); gl3 = __ldcs(g_Gl + gidx + 768 + hg); gu3 = __ldcs(g_Gu + gidx + 768 + hg);
        }

        if (t > 0) {
            __syncthreads();
            if (tid == 0) {
                asm volatile("red.release.gpu.global.add.u32 [%0], 1;" :: "l"(barp) : "memory");
                unsigned int v;
                do {
                    asm volatile("ld.acquire.gpu.global.u32 %0, [%1];" : "=r"(v) : "l"(barp) : "memory");
                } while (v < (unsigned)t * 16u);
            }
            __syncthreads();
        }

        // stage previous h: sH[k][0..7]=v, [8..15]=m, [16..23]=r
        if (t == 0) {
            for (int idx = tid; idx < 2048; idx += NTHR) {
                const int k = idx >> 3, bb = idx & 7;
                const float v = h0[(gb * 8 + bb) * HH + k];
                sH[k * 24 + bb]      = v;
                sH[k * 24 + 8 + bb]  = v;
                sH[k * 24 + 16 + bb] = 0.f;
            }
        } else {
            const float4* src = g_Hf4 + ((t - 1) & 1) * (HH * BB) + gb * 8;
            for (int idx = tid; idx < 2048; idx += NTHR) {
                const int k = idx >> 3, bb = idx & 7;
                const float4 f = __ldcg(src + k * BB + bb);
                sH[k * 24 + bb]      = f.x;
                sH[k * 24 + 8 + bb]  = f.y;
                sH[k * 24 + 16 + bb] = f.z;
            }
        }
        __syncthreads();

        // k-loop: W from regs, h broadcast from smem
        u64 accv[4] = {0ull, 0ull, 0ull, 0ull};
        u64 accm[4] = {0ull, 0ull, 0ull, 0ull};
        u64 accr[4] = {0ull, 0ull, 0ull, 0ull};
#pragma unroll
        for (int kk = 0; kk < KSL; kk++) {
            const ulonglong2* hk = (const ulonglong2*)(sH + (kbase + kk) * 24);
            const ulonglong2 hva = hk[0];   // hv b0b1, b2b3
            const ulonglong2 hvb = hk[1];   // hv b4b5, b6b7
            const ulonglong2 hma = hk[2];
            const ulonglong2 hmb = hk[3];
            const ulonglong2 hra = hk[4];
            const ulonglong2 hrb = hk[5];
            const float w = wreg[kk];
            const u64 wd = pk(w, w);
            const u64 wa = wd & 0x7FFFFFFF7FFFFFFFull;
            accv[0] = fma2(hva.x, wd, accv[0]);
            accv[1] = fma2(hva.y, wd, accv[1]);
            accv[2] = fma2(hvb.x, wd, accv[2]);
            accv[3] = fma2(hvb.y, wd, accv[3]);
            accm[0] = fma2(hma.x, wd, accm[0]);
            accm[1] = fma2(hma.y, wd, accm[1]);
            accm[2] = fma2(hmb.x, wd, accm[2]);
            accm[3] = fma2(hmb.y, wd, accm[3]);
            accr[0] = fma2(hra.x, wa, accr[0]);
            accr[1] = fma2(hra.y, wa, accr[1]);
            accr[2] = fma2(hrb.x, wa, accr[2]);
            accr[3] = fma2(hrb.y, wa, accr[3]);
        }

        // ksplit reduction: kgroup>0 publish partials
        if (kgroup > 0) {
            u64* r = sRed + (size_t)tid * 14;
            ((ulonglong2*)r)[0] = make_ulonglong2(accv[0], accv[1]);
            ((ulonglong2*)r)[1] = make_ulonglong2(accv[2], accv[3]);
            ((ulonglong2*)r)[2] = make_ulonglong2(accm[0], accm[1]);
            ((ulonglong2*)r)[3] = make_ulonglong2(accm[2], accm[3]);
            ((ulonglong2*)r)[4] = make_ulonglong2(accr[0], accr[1]);
            ((ulonglong2*)r)[5] = make_ulonglong2(accr[2], accr[3]);
        }
        __syncthreads();

        if (tid < 64) {
#pragma unroll
            for (int s = 1; s < 8; s++) {
                const u64* r = sRed + (size_t)(s * 64 + m) * 14;
                const ulonglong2 p0 = ((const ulonglong2*)r)[0];
                const ulonglong2 p1 = ((const ulonglong2*)r)[1];
                const ulonglong2 p2 = ((const ulonglong2*)r)[2];
                const ulonglong2 p3 = ((const ulonglong2*)r)[3];
                const ulonglong2 p4 = ((const ulonglong2*)r)[4];
                const ulonglong2 p5 = ((const ulonglong2*)r)[5];
                accv[0] = add2(accv[0], p0.x); accv[1] = add2(accv[1], p0.y);
                accv[2] = add2(accv[2], p1.x); accv[3] = add2(accv[3], p1.y);
                accm[0] = add2(accm[0], p2.x); accm[1] = add2(accm[1], p2.y);
                accm[2] = add2(accm[2], p3.x); accm[3] = add2(accm[3], p3.y);
                accr[0] = add2(accr[0], p4.x); accr[1] = add2(accr[1], p4.y);
                accr[2] = add2(accr[2], p5.x); accr[3] = add2(accr[3], p5.y);
            }
            // transpose to sT: u64 idx = I*64 + hL*4 + p  (I: 0..3 v, 4..7 m, 8..11 r)
            ((ulonglong2*)&sT[(0 + g) * 64 + hL * 4])[0] = make_ulonglong2(accv[0], accv[1]);
            ((ulonglong2*)&sT[(0 + g) * 64 + hL * 4])[1] = make_ulonglong2(accv[2], accv[3]);
            ((ulonglong2*)&sT[(4 + g) * 64 + hL * 4])[0] = make_ulonglong2(accm[0], accm[1]);
            ((ulonglong2*)&sT[(4 + g) * 64 + hL * 4])[1] = make_ulonglong2(accm[2], accm[3]);
            ((ulonglong2*)&sT[(8 + g) * 64 + hL * 4])[0] = make_ulonglong2(accr[0], accr[1]);
            ((ulonglong2*)&sT[(8 + g) * 64 + hL * 4])[1] = make_ulonglong2(accr[2], accr[3]);
        }
        __syncthreads();

        // pointwise (tid < 128): cell (ph, pb)
        if (tid < 128) {
            const int co = ph * 8 + pb;
            const float av0 = sTf[(0) * 128 + co], av1 = sTf[(1) * 128 + co];
            const float av2 = sTf[(2) * 128 + co], av3 = sTf[(3) * 128 + co];
            const float am0 = sTf[(4) * 128 + co], am1 = sTf[(5) * 128 + co];
            const float am2 = sTf[(6) * 128 + co], am3 = sTf[(7) * 128 + co];
            const float ar0 = sTf[(8) * 128 + co], ar1 = sTf[(9) * 128 + co];
            const float ar2 = sTf[(10) * 128 + co], ar3 = sTf[(11) * 128 + co];

            const float pv0 = gv0 + av0, pl0 = gl0 + am0 - ar0, pu0 = gu0 + am0 + ar0;
            const float pv1 = gv1 + av1, pl1 = gl1 + am1 - ar1, pu1 = gu1 + am1 + ar1;
            const float pv2 = gv2 + av2, pl2 = gl2 + am2 - ar2, pu2 = gu2 + am2 + ar2;
            const float pv3 = gv3 + av3, pl3 = gl3 + am3 - ar3, pu3 = gu3 + am3 + ar3;

            const float iv = sigf(pv0), il = sigf(pl0), iu = sigf(pu0);
            const float fv = sigf(pv1), fl = sigf(pl1), fu = sigf(pu1);
            const float gv = tanhf_(pv2), gl = tanhf_(pl2), gu = tanhf_(pu2);
            const float ov = sigf(pv3), ol = sigf(pl3), ou = sigf(pu3);

            const float t1 = fl * cl, t2 = fl * cu, t3 = fu * cl, t4 = fu * cu;
            const float s1 = il * gl, s2 = il * gu, s3 = iu * gl, s4 = iu * gu;
            cv = fv * cv + iv * gv;
            cl = min4f(t1, t2, t3, t4) + min4f(s1, s2, s3, s4);
            cu = max4f(t1, t2, t3, t4) + max4f(s1, s2, s3, s4);

            const float tv = tanhf_(cv), tl = tanhf_(cl), tu = tanhf_(cu);
            const float u1 = ol * tl, u2 = ol * tu, u3 = ou * tl, u4 = ou * tu;
            const float hn_l = min4f(u1, u2, u3, u4);
            const float hn_u = max4f(u1, u2, u3, u4);
            const float hn_v = ov * tv;

            const float hm = 0.5f * (hn_l + hn_u);
            const float hr = 0.5f * (hn_u - hn_l);
            __stcg(g_Hf4 + (t & 1) * (HH * BB) + hg * BB + bglob,
                   make_float4(hn_v, hm, hr, 0.f));

            const size_t obase = ((size_t)(bglob << 9) + t) * HH + hg;
            out[obase] = hn_v;
            out[(size_t)BB * TT * HH + obase] = hn_l;
            out[2 * (size_t)BB * TT * HH + obase] = hn_u;
        }
    }
}

// ---------------------------------------------------------------------------
// Launch
// ---------------------------------------------------------------------------
extern "C" void kernel_launch(void* const* d_in, const int* in_sizes, int n_in,
                              void* d_out, int out_size)
{
    const float* xv   = (const float*)d_in[0];
    const float* xl   = (const float*)d_in[1];
    const float* xu   = (const float*)d_in[2];
    const float* Wih  = (const float*)d_in[3];
    const float* Whh  = (const float*)d_in[4];
    const float* bias = (const float*)d_in[5];
    const float* h0   = (const float*)d_in[6];
    const float* c0   = (const float*)d_in[7];
    float* out = (float*)d_out;

    const int smem_bytes = SMEM_FLOATS * sizeof(float);   // 88 KB
    cudaFuncSetAttribute(scan_kernel, cudaFuncAttributeMaxDynamicSharedMemorySize, smem_bytes);

    gx_gemm_kernel<<<dim3(G4H / GN, (BB * TT) / GM), 256>>>(xv, xl, xu, Wih, bias);
    scan_kernel<<<NCTA, NTHR, smem_bytes>>>(Whh, h0, c0, out);
}